// round 15
// baseline (speedup 1.0000x reference)
#include <cuda_runtime.h>
#include <cuda_bf16.h>
#include <cstdint>

// ---------------------------------------------------------------------------
// SSA — B=32, C=512, N=1024. INT8 IMMA (m16n8k32 s8s8s32) version.
//   qkv conv : s8 GEMM M=1536 (W x2874, x x25; BN per-channel scale-invariant)
//              epilogue: bf16 store + per-channel stats atomics
//   BN/LIF; q -> s8 {0,1} q^T, k/v -> bitpacked; kv via AND+POPC -> s8 kv/16
//   attn^T   : s8 GEMM, spike = (acc >= 1)  -> s8 {0,1}
//   proj     : s8 GEMM (W x2874), fp32 bias epilogue + stats
//   BN/LIF -> d_out
// ---------------------------------------------------------------------------

namespace {
constexpr int  BB  = 32;
constexpr int  CC  = 512;
constexpr int  NN  = 1024;
constexpr long BCN = (long)BB * CC * NN;
constexpr long SY  = (long)3 * CC * NN;
constexpr float TAUf = 1.1f;
constexpr float EPSf = 1e-5f;
constexpr float SW   = 2874.0f;           // 127 / (1/sqrt(512))
constexpr float SX   = 25.0f;             // x clip at ~5 sigma
constexpr float INV_QKV = 1.0f / (SW * SX);
constexpr float INV_PW  = 1.0f / SW;
}

// scratch (device globals)
__device__ __nv_bfloat16 g_y[BB * 3 * CC * NN];     // qkv conv out (bf16)
__device__ int8_t        g_xT8[BB * CC * NN];       // x^T s8 (x25) [b][n][c]
__device__ int8_t        g_qT8[BB * CC * NN];       // q spikes^T s8 [b][n][c]
__device__ unsigned      g_kbits[BB * CC * NN / 32];
__device__ unsigned      g_vbits[BB * CC * NN / 32];
__device__ int8_t        g_kvT8[BB * CC * CC];      // round(kv/16) s8 [b][d][c]
__device__ int8_t        g_attnT8[BB * CC * NN];    // attn spikes s8 [b][n][d]
__device__ float         g_proj[BB * CC * NN];      // proj out fp32
__device__ int8_t        g_wqkv8[3 * CC * CC];      // stacked qkv weights s8
__device__ int8_t        g_pw8[CC * CC];            // proj weight s8
__device__ float         g_ssum[4 * CC];
__device__ float         g_ssum2[4 * CC];
__device__ float         g_mean[4 * CC];
__device__ float         g_inv[4 * CC];

// ---------------------------------------------------------------------------
__device__ __forceinline__ uint32_t smem_u32(const void* p) {
    return (uint32_t)__cvta_generic_to_shared(p);
}
__device__ __forceinline__ void cp_async16(uint32_t s, const void* g) {
    asm volatile("cp.async.cg.shared.global [%0], [%1], 16;" :: "r"(s), "l"(g));
}
__device__ __forceinline__ void ldm_x4(uint32_t& r0, uint32_t& r1,
                                       uint32_t& r2, uint32_t& r3, uint32_t a) {
    asm volatile("ldmatrix.sync.aligned.m8n8.x4.shared.b16 {%0,%1,%2,%3}, [%4];"
                 : "=r"(r0), "=r"(r1), "=r"(r2), "=r"(r3) : "r"(a));
}
__device__ __forceinline__ void mma_s8(int* c, const uint32_t* a, const uint32_t* b) {
    asm volatile(
        "mma.sync.aligned.m16n8k32.row.col.s32.s8.s8.s32 "
        "{%0,%1,%2,%3},{%4,%5,%6,%7},{%8,%9},{%0,%1,%2,%3};"
        : "+r"(c[0]), "+r"(c[1]), "+r"(c[2]), "+r"(c[3])
        : "r"(a[0]), "r"(a[1]), "r"(a[2]), "r"(a[3]), "r"(b[0]), "r"(b[1]));
}
__device__ __forceinline__ int8_t quant8(float v, float s) {
    float q = rintf(fminf(fmaxf(v * s, -127.f), 127.f));
    return (int8_t)(int)q;
}

// ---------------------------------------------------------------------------
// INT8 GEMM: C[m,n] = sum_k A[m][k] * BT[n][k]   (s8 data viewed as u16 pairs)
//   lda/ldb/K in u16 units (1 u16 = 2 s8 k-elements).
//   EPI: 0 = bf16 store (acc*INV_QKV) + stats
//        1 = f32 store (acc*INV_PW + bias) + stats
//        2 = s8 spike store (acc >= 1)
// CTA tile 128x128(out), K-chunk 64 s8, 8 warps (64x32), double-buffered.
// ---------------------------------------------------------------------------
template<int EPI>
__global__ void __launch_bounds__(256)
gemm_s8(const uint16_t* __restrict__ A, int lda, long sA,
        const uint16_t* __restrict__ BT, int ldb, long sB,
        void* __restrict__ Cout, int ldc, long sC,
        int K, const float* __restrict__ bias,
        float* __restrict__ ssum, float* __restrict__ ssum2)
{
    constexpr int LDS = 40;
    __shared__ uint16_t As[2][128 * LDS];
    __shared__ uint16_t Bs[2][128 * LDS];

    const int bz = blockIdx.z;
    const uint16_t* Ab = A + (long)bz * sA;
    const uint16_t* Bb = BT + (long)bz * sB;
    const int m0 = blockIdx.y * 128, n0 = blockIdx.x * 128;
    const int tid = threadIdx.x;
    const int lane = tid & 31, warp = tid >> 5;
    const int wm = (warp & 1) * 64, wn = (warp >> 1) * 32;

    int acc[4][4][4];
#pragma unroll
    for (int i = 0; i < 4; i++)
#pragma unroll
        for (int j = 0; j < 4; j++)
#pragma unroll
            for (int r = 0; r < 4; r++) acc[i][j][r] = 0;

    auto issue = [&](int st, int k0) {       // k0 in u16 units, chunk = 32 u16
#pragma unroll
        for (int i = 0; i < 2; i++) {
            int c = tid + i * 256;
            int row = c >> 2, kc = (c & 3) << 3;
            cp_async16(smem_u32(&As[st][row * LDS + kc]),
                       Ab + (long)(m0 + row) * lda + k0 + kc);
            cp_async16(smem_u32(&Bs[st][row * LDS + kc]),
                       Bb + (long)(n0 + row) * ldb + k0 + kc);
        }
        asm volatile("cp.async.commit_group;");
    };

    const int KT = K / 32;                   // 32 u16 = 64 s8 per chunk
    issue(0, 0);
    for (int kt = 0; kt < KT; kt++) {
        if (kt + 1 < KT) {
            issue((kt + 1) & 1, (kt + 1) * 32);
            asm volatile("cp.async.wait_group 1;");
        } else {
            asm volatile("cp.async.wait_group 0;");
        }
        __syncthreads();
        const uint16_t* as = As[kt & 1];
        const uint16_t* bs = Bs[kt & 1];
#pragma unroll
        for (int kk = 0; kk < 2; kk++) {     // each kk = 16 u16 = 32 s8 k
            uint32_t af[4][4], bf[4][2];
#pragma unroll
            for (int mt = 0; mt < 4; mt++) {
                int row = wm + mt * 16 + (lane & 15);
                int kcol = kk * 16 + (lane >> 4) * 8;
                ldm_x4(af[mt][0], af[mt][1], af[mt][2], af[mt][3],
                       smem_u32(&as[row * LDS + kcol]));
            }
#pragma unroll
            for (int p = 0; p < 2; p++) {
                int g = lane >> 3;
                int row = wn + p * 16 + (g >> 1) * 8 + (lane & 7);
                int kcol = kk * 16 + (g & 1) * 8;
                uint32_t r0, r1, r2, r3;
                ldm_x4(r0, r1, r2, r3, smem_u32(&bs[row * LDS + kcol]));
                bf[p * 2][0] = r0; bf[p * 2][1] = r1;
                bf[p * 2 + 1][0] = r2; bf[p * 2 + 1][1] = r3;
            }
#pragma unroll
            for (int mt = 0; mt < 4; mt++)
#pragma unroll
                for (int nt = 0; nt < 4; nt++)
                    mma_s8(acc[mt][nt], af[mt], bf[nt]);
        }
        __syncthreads();
    }

    // epilogue
#pragma unroll
    for (int mt = 0; mt < 4; mt++) {
        int row = m0 + wm + mt * 16 + (lane >> 2);
        float b0 = 0.f, b8 = 0.f;
        if (EPI == 1) { b0 = bias[row]; b8 = bias[row + 8]; }
        float sl = 0.f, ql = 0.f, sh = 0.f, qh = 0.f;
#pragma unroll
        for (int nt = 0; nt < 4; nt++) {
            int col = n0 + wn + nt * 8 + (lane & 3) * 2;
            int* a4 = acc[mt][nt];
            if (EPI == 2) {
                int8_t* Cb = (int8_t*)Cout + (long)bz * sC;
                int8_t s0 = (a4[0] >= 1) ? 1 : 0;
                int8_t s1 = (a4[1] >= 1) ? 1 : 0;
                int8_t s2 = (a4[2] >= 1) ? 1 : 0;
                int8_t s3 = (a4[3] >= 1) ? 1 : 0;
                *(short*)&Cb[(long)row * ldc + col] =
                    (short)((unsigned char)s0 | ((unsigned char)s1 << 8));
                *(short*)&Cb[(long)(row + 8) * ldc + col] =
                    (short)((unsigned char)s2 | ((unsigned char)s3 << 8));
            } else if (EPI == 0) {
                __nv_bfloat16* Cb = (__nv_bfloat16*)Cout + (long)bz * sC;
                float v0 = (float)a4[0] * INV_QKV, v1 = (float)a4[1] * INV_QKV;
                float v2 = (float)a4[2] * INV_QKV, v3 = (float)a4[3] * INV_QKV;
                *(__nv_bfloat162*)&Cb[(long)row * ldc + col] = __floats2bfloat162_rn(v0, v1);
                *(__nv_bfloat162*)&Cb[(long)(row + 8) * ldc + col] = __floats2bfloat162_rn(v2, v3);
                sl += v0 + v1; ql = fmaf(v0, v0, fmaf(v1, v1, ql));
                sh += v2 + v3; qh = fmaf(v2, v2, fmaf(v3, v3, qh));
            } else {
                float* Cb = (float*)Cout + (long)bz * sC;
                float v0 = (float)a4[0] * INV_PW + b0, v1 = (float)a4[1] * INV_PW + b0;
                float v2 = (float)a4[2] * INV_PW + b8, v3 = (float)a4[3] * INV_PW + b8;
                *(float2*)&Cb[(long)row * ldc + col] = make_float2(v0, v1);
                *(float2*)&Cb[(long)(row + 8) * ldc + col] = make_float2(v2, v3);
                sl += v0 + v1; ql = fmaf(v0, v0, fmaf(v1, v1, ql));
                sh += v2 + v3; qh = fmaf(v2, v2, fmaf(v3, v3, qh));
            }
        }
        if (EPI != 2) {
            sl += __shfl_xor_sync(0xffffffffu, sl, 1);
            sl += __shfl_xor_sync(0xffffffffu, sl, 2);
            ql += __shfl_xor_sync(0xffffffffu, ql, 1);
            ql += __shfl_xor_sync(0xffffffffu, ql, 2);
            sh += __shfl_xor_sync(0xffffffffu, sh, 1);
            sh += __shfl_xor_sync(0xffffffffu, sh, 2);
            qh += __shfl_xor_sync(0xffffffffu, qh, 1);
            qh += __shfl_xor_sync(0xffffffffu, qh, 2);
            if ((lane & 3) == 0) {
                atomicAdd(&ssum[row], sl);  atomicAdd(&ssum2[row], ql);
                atomicAdd(&ssum[row + 8], sh); atomicAdd(&ssum2[row + 8], qh);
            }
        }
    }
}

// ---------------------------------------------------------------------------
__global__ void __launch_bounds__(256)
zero_stats(float* __restrict__ a, float* __restrict__ b)
{
    int i = blockIdx.x * 256 + threadIdx.x;
    if (i < 4 * CC) { a[i] = 0.f; b[i] = 0.f; }
}

__global__ void __launch_bounds__(256)
finalize_stats(const float* __restrict__ ss, const float* __restrict__ ss2,
               float* __restrict__ mean, float* __restrict__ inv, int nch)
{
    int i = blockIdx.x * 256 + threadIdx.x;
    if (i < nch) {
        const float invn = 1.f / (float)(BB * NN);
        float m = ss[i] * invn;
        float var = ss2[i] * invn - m * m;
        mean[i] = m;
        inv[i] = rsqrtf(var + EPSf);
    }
}

// weights -> s8 (scale SW; BN per-channel scale-invariance absorbs it)
__global__ void __launch_bounds__(256)
convert_weights(const float* __restrict__ qw, const float* __restrict__ kw,
                const float* __restrict__ vw, const float* __restrict__ pw,
                int8_t* __restrict__ wqkv, int8_t* __restrict__ pwo)
{
    int i = blockIdx.x * 256 + threadIdx.x;
    wqkv[i]               = quant8(qw[i], SW);
    wqkv[i + CC * CC]     = quant8(kw[i], SW);
    wqkv[i + 2 * CC * CC] = quant8(vw[i], SW);
    pwo[i]                = quant8(pw[i], SW);
}

// x [b][c][n] fp32 -> xT s8 (x25) [b][n][c]
__global__ void __launch_bounds__(256)
xT_kernel(const float* __restrict__ x, int8_t* __restrict__ xT)
{
    __shared__ float t[32][33];
    int b = blockIdx.z, n0 = blockIdx.x * 32, c0 = blockIdx.y * 32;
    int tx = threadIdx.x, ty = threadIdx.y;
    const float* xb = x + (long)b * CC * NN;
    int8_t* ob = xT + (long)b * NN * CC;
#pragma unroll
    for (int i = 0; i < 32; i += 8)
        t[ty + i][tx] = xb[(long)(c0 + ty + i) * NN + n0 + tx];
    __syncthreads();
#pragma unroll
    for (int i = 0; i < 32; i += 8)
        ob[(long)(n0 + ty + i) * CC + c0 + tx] = quant8(t[tx][ty + i], SX);
}

// q: BN + threshold + transpose -> s8 qT [b][n][c]
__global__ void __launch_bounds__(256)
spike_qT_kernel(const __nv_bfloat16* __restrict__ y, long bstride,
                const float* __restrict__ mean, const float* __restrict__ inv,
                int8_t* __restrict__ qT)
{
    __shared__ float t[32][33];
    int b = blockIdx.z, n0 = blockIdx.x * 32, c0 = blockIdx.y * 32;
    int tx = threadIdx.x, ty = threadIdx.y;
    const __nv_bfloat16* yb = y + (long)b * bstride;
#pragma unroll
    for (int i = 0; i < 32; i += 8) {
        int c = c0 + ty + i;
        float v = __bfloat162float(yb[(long)c * NN + n0 + tx]);
        float bn = inv[c] * (v - mean[c]);
        t[ty + i][tx] = (bn / TAUf - 1.0f >= 0.f) ? 1.f : 0.f;
    }
    __syncthreads();
    int8_t* ob = qT + (long)b * NN * CC;
#pragma unroll
    for (int i = 0; i < 32; i += 8)
        ob[(long)(n0 + ty + i) * CC + c0 + tx] = (t[tx][ty + i] != 0.f) ? 1 : 0;
}

// k/v: BN + threshold -> bitpacked (permuted-but-consistent layout)
__global__ void __launch_bounds__(256)
spike_pack_kernel(const __nv_bfloat16* __restrict__ y, long bstride,
                  const float* __restrict__ mean, const float* __restrict__ inv,
                  unsigned* __restrict__ bits)
{
    long t = (long)blockIdx.x * 256 + threadIdx.x;
    long e = t * 4;
    int b = (int)(e / ((long)CC * NN));
    long r = e - (long)b * CC * NN;
    int c = (int)(r >> 10);
    const __nv_bfloat16* p = y + (long)b * bstride + r;
    uint2 raw = *(const uint2*)p;
    __nv_bfloat162 p01 = *(__nv_bfloat162*)&raw.x;
    __nv_bfloat162 p23 = *(__nv_bfloat162*)&raw.y;
    float g = inv[c], m = mean[c];
    float v0 = __low2float(p01), v1 = __high2float(p01);
    float v2 = __low2float(p23), v3 = __high2float(p23);
    unsigned m0 = __ballot_sync(0xffffffffu, (g * (v0 - m)) / TAUf - 1.f >= 0.f);
    unsigned m1 = __ballot_sync(0xffffffffu, (g * (v1 - m)) / TAUf - 1.f >= 0.f);
    unsigned m2 = __ballot_sync(0xffffffffu, (g * (v2 - m)) / TAUf - 1.f >= 0.f);
    unsigned m3 = __ballot_sync(0xffffffffu, (g * (v3 - m)) / TAUf - 1.f >= 0.f);
    int lane = threadIdx.x & 31;
    long e0 = e - (long)lane * 4;
    unsigned w = (lane == 0) ? m0 : (lane == 1) ? m1 : (lane == 2) ? m2 : m3;
    if (lane < 4) bits[(e0 >> 5) + lane] = w;
}

// kvT[b][d][c] = round(popc(k[c] & v[d]) / 16) -> s8
__global__ void __launch_bounds__(256)
kv_popc_kernel(const unsigned* __restrict__ kb, const unsigned* __restrict__ vb,
               int8_t* __restrict__ kvT)
{
    __shared__ unsigned ks[32][65];
    __shared__ unsigned vs[32][65];
    const int bz = blockIdx.z;
    const int c0 = blockIdx.y * 64;
    const int d0 = blockIdx.x * 64;
    const unsigned* kbb = kb + (long)bz * CC * (NN / 32);
    const unsigned* vbb = vb + (long)bz * CC * (NN / 32);
    const int tid = threadIdx.x;
#pragma unroll
    for (int it = 0; it < 8; it++) {
        int idx = tid + it * 256;
        int r = idx >> 5, w = idx & 31;
        ks[w][r] = kbb[(long)(c0 + r) * 32 + w];
        vs[w][r] = vbb[(long)(d0 + r) * 32 + w];
    }
    __syncthreads();
    const int tm = (tid >> 4) * 4;   // c
    const int tn = (tid & 15) * 4;   // d
    int cnt[4][4];
#pragma unroll
    for (int i = 0; i < 4; i++)
#pragma unroll
        for (int j = 0; j < 4; j++) cnt[i][j] = 0;
#pragma unroll
    for (int w = 0; w < 32; w++) {
        unsigned a[4], b[4];
#pragma unroll
        for (int i = 0; i < 4; i++) a[i] = ks[w][tm + i];
#pragma unroll
        for (int j = 0; j < 4; j++) b[j] = vs[w][tn + j];
#pragma unroll
        for (int i = 0; i < 4; i++)
#pragma unroll
            for (int j = 0; j < 4; j++)
                cnt[i][j] += __popc(a[i] & b[j]);
    }
    int8_t* ob = kvT + (long)bz * CC * CC;
#pragma unroll
    for (int j = 0; j < 4; j++) {
        long base = (long)(d0 + tn + j) * CC + c0 + tm;   // tm % 4 == 0
        unsigned q0 = (unsigned)((cnt[0][j] + 8) >> 4);
        unsigned q1 = (unsigned)((cnt[1][j] + 8) >> 4);
        unsigned q2 = (unsigned)((cnt[2][j] + 8) >> 4);
        unsigned q3 = (unsigned)((cnt[3][j] + 8) >> 4);
        *(unsigned*)&ob[base] = q0 | (q1 << 8) | (q2 << 16) | (q3 << 24);
    }
}

// final BN + LIF -> d_out
__global__ void __launch_bounds__(256)
spike_final_kernel(const float* __restrict__ y,
                   const float* __restrict__ mean, const float* __restrict__ inv,
                   float* __restrict__ out)
{
    long t = (long)blockIdx.x * 256 + threadIdx.x;
    long e = t * 4;
    int c = (int)((e >> 10) & (CC - 1));
    float g = inv[c], m = mean[c];
    float4 v = *(const float4*)&y[e];
    float4 o;
    o.x = ((g * (v.x - m)) / TAUf - 1.f >= 0.f) ? 1.f : 0.f;
    o.y = ((g * (v.y - m)) / TAUf - 1.f >= 0.f) ? 1.f : 0.f;
    o.z = ((g * (v.z - m)) / TAUf - 1.f >= 0.f) ? 1.f : 0.f;
    o.w = ((g * (v.w - m)) / TAUf - 1.f >= 0.f) ? 1.f : 0.f;
    *(float4*)&out[e] = o;
}

__global__ void __launch_bounds__(256)
fold_affine(float* __restrict__ mean, float* __restrict__ inv,
            const float* __restrict__ gamma, const float* __restrict__ beta, int nch)
{
    int i = blockIdx.x * 256 + threadIdx.x;
    if (i < nch) {
        float g = gamma[i] * inv[i];
        float m = mean[i];
        mean[i] = m - beta[i] / g;
        inv[i] = g;
    }
}

// ---------------------------------------------------------------------------
extern "C" void kernel_launch(void* const* d_in, const int* in_sizes, int n_in,
                              void* d_out, int out_size)
{
    const float* x      = (const float*)d_in[0];
    const float* q_w    = (const float*)d_in[1];
    const float* q_g    = (const float*)d_in[2];
    const float* q_b    = (const float*)d_in[3];
    const float* k_w    = (const float*)d_in[4];
    const float* k_g    = (const float*)d_in[5];
    const float* k_b    = (const float*)d_in[6];
    const float* v_w    = (const float*)d_in[7];
    const float* v_g    = (const float*)d_in[8];
    const float* v_b    = (const float*)d_in[9];
    const float* p_w    = (const float*)d_in[10];
    const float* p_g    = (const float*)d_in[11];
    const float* p_beta = (const float*)d_in[12];
    const float* p_bias = (const float*)d_in[13];

    void* p;
    cudaGetSymbolAddress(&p, g_y);      __nv_bfloat16* gy     = (__nv_bfloat16*)p;
    cudaGetSymbolAddress(&p, g_xT8);    int8_t*        gxT    = (int8_t*)p;
    cudaGetSymbolAddress(&p, g_qT8);    int8_t*        gqT    = (int8_t*)p;
    cudaGetSymbolAddress(&p, g_kbits);  unsigned*      gkb    = (unsigned*)p;
    cudaGetSymbolAddress(&p, g_vbits);  unsigned*      gvb    = (unsigned*)p;
    cudaGetSymbolAddress(&p, g_kvT8);   int8_t*        gkvT   = (int8_t*)p;
    cudaGetSymbolAddress(&p, g_attnT8); int8_t*        gattT  = (int8_t*)p;
    cudaGetSymbolAddress(&p, g_proj);   float*         gpr    = (float*)p;
    cudaGetSymbolAddress(&p, g_wqkv8);  int8_t*        gwqkv  = (int8_t*)p;
    cudaGetSymbolAddress(&p, g_pw8);    int8_t*        gpw    = (int8_t*)p;
    cudaGetSymbolAddress(&p, g_ssum);   float*         gss    = (float*)p;
    cudaGetSymbolAddress(&p, g_ssum2);  float*         gss2   = (float*)p;
    cudaGetSymbolAddress(&p, g_mean);   float*         gmean  = (float*)p;
    cudaGetSymbolAddress(&p, g_inv);    float*         ginv   = (float*)p;

    // strides in u16 units for s8 operands (2 s8 per u16)
    const int  ldK   = CC / 2;                 // 256 u16 per 512-s8 row
    const long sB_x  = (long)NN * CC / 2;      // xT / qT / attnT per-batch (u16)
    const long sB_kv = (long)CC * CC / 2;      // kvT per-batch (u16)
    const long sCN   = (long)CC * NN;
    const unsigned nblk4 = (unsigned)(BCN / 4 / 256);
    dim3 t32(32, 8);
    dim3 gT(NN / 32, CC / 32, BB);

    // 0) zero stats, weight conversion, x transpose
    zero_stats<<<8, 256>>>(gss, gss2);
    convert_weights<<<(CC * CC) / 256, 256>>>(q_w, k_w, v_w, p_w, gwqkv, gpw);
    xT_kernel<<<gT, t32>>>(x, gxT);

    // 1) fused qkv conv GEMM (s8 IMMA): M=1536, N=1024, K=512 s8 (256 u16)
    gemm_s8<0><<<dim3(NN / 128, 1536 / 128, BB), 256>>>(
        (const uint16_t*)gwqkv, ldK, 0,
        (const uint16_t*)gxT, ldK, sB_x,
        gy, NN, SY, CC / 2, nullptr, gss, gss2);

    // 2) finalize qkv stats + fold affine
    finalize_stats<<<6, 256>>>(gss, gss2, gmean, ginv, 3 * CC);
    fold_affine<<<2, 256>>>(gmean + 0 * CC, ginv + 0 * CC, q_g, q_b, CC);
    fold_affine<<<2, 256>>>(gmean + 1 * CC, ginv + 1 * CC, k_g, k_b, CC);
    fold_affine<<<2, 256>>>(gmean + 2 * CC, ginv + 2 * CC, v_g, v_b, CC);

    // 3) spikes: q -> s8 transposed, k/v -> bitpacked
    spike_qT_kernel<<<gT, t32>>>(gy, SY, gmean, ginv, gqT);
    spike_pack_kernel<<<nblk4, 256>>>(gy + 1 * sCN, SY, gmean + 1 * CC, ginv + 1 * CC, gkb);
    spike_pack_kernel<<<nblk4, 256>>>(gy + 2 * sCN, SY, gmean + 2 * CC, ginv + 2 * CC, gvb);

    // 4) kv^T via popcount -> s8 (kv/16)
    kv_popc_kernel<<<dim3(CC / 64, CC / 64, BB), 256>>>(gkb, gvb, gkvT);

    // 5) attn^T GEMM (s8) + spike (acc>=1): M=1024, N=512, K=512 s8
    gemm_s8<2><<<dim3(CC / 128, NN / 128, BB), 256>>>(
        (const uint16_t*)gqT, ldK, sB_x,
        (const uint16_t*)gkvT, ldK, sB_kv,
        gattT, CC, sCN, CC / 2, nullptr, nullptr, nullptr);

    // 6) proj GEMM (s8) + bias + stats: M=512, N=1024, K=512 s8
    gemm_s8<1><<<dim3(NN / 128, CC / 128, BB), 256>>>(
        (const uint16_t*)gpw, ldK, 0,
        (const uint16_t*)gattT, ldK, sB_x,
        gpr, NN, sCN, CC / 2, p_bias, gss + 3 * CC, gss2 + 3 * CC);

    // 7) finalize proj stats + final spike
    finalize_stats<<<2, 256>>>(gss + 3 * CC, gss2 + 3 * CC,
                               gmean + 3 * CC, ginv + 3 * CC, CC);
    fold_affine<<<2, 256>>>(gmean + 3 * CC, ginv + 3 * CC, p_g, p_beta, CC);
    spike_final_kernel<<<nblk4, 256>>>(gpr, gmean + 3 * CC, ginv + 3 * CC,
                                       (float*)d_out);
}

// round 16
// speedup vs baseline: 1.6373x; 1.6373x over previous
#include <cuda_runtime.h>
#include <cuda_bf16.h>
#include <cuda_fp16.h>
#include <cstdint>

// ---------------------------------------------------------------------------
// SSA — B=32, C=512, N=1024. mma.sync; qkv+attn use fp16 MMA with FP16
// accumulators (half the acc registers, candidate 2x rate); proj stays
// bf16 with fp32 accum (final-BN precision). Fused BN stats in epilogues.
// ---------------------------------------------------------------------------

namespace {
constexpr int  BB  = 32;
constexpr int  CC  = 512;
constexpr int  NN  = 1024;
constexpr long BCN = (long)BB * CC * NN;
constexpr long SY  = (long)3 * CC * NN;
constexpr float TAUf = 1.1f;
constexpr float EPSf = 1e-5f;
}

// scratch (device globals)
__device__ __nv_bfloat16 g_y[BB * 3 * CC * NN];     // qkv conv out (bf16)
__device__ __half        g_xT[BB * CC * NN];        // x^T fp16 [b][n][c]
__device__ __half        g_qT[BB * CC * NN];        // q spikes^T fp16
__device__ unsigned      g_kbits[BB * CC * NN / 32];
__device__ unsigned      g_vbits[BB * CC * NN / 32];
__device__ __half        g_kvT[BB * CC * CC];       // kv^T fp16 (exact ints)
__device__ __nv_bfloat16 g_attnT[BB * CC * NN];     // attn spikes bf16 [b][n][d]
__device__ float         g_proj[BB * CC * NN];      // proj out fp32
__device__ __half        g_wqkv[3 * CC * CC];       // stacked qkv weights fp16
__device__ __nv_bfloat16 g_pw[CC * CC];             // proj weight bf16
__device__ float         g_ssum[4 * CC];
__device__ float         g_ssum2[4 * CC];
__device__ float         g_mean[4 * CC];
__device__ float         g_inv[4 * CC];

// ---------------------------------------------------------------------------
__device__ __forceinline__ uint32_t smem_u32(const void* p) {
    return (uint32_t)__cvta_generic_to_shared(p);
}
__device__ __forceinline__ void cp_async16(uint32_t s, const void* g) {
    asm volatile("cp.async.cg.shared.global [%0], [%1], 16;" :: "r"(s), "l"(g));
}
__device__ __forceinline__ void ldm_x4(uint32_t& r0, uint32_t& r1,
                                       uint32_t& r2, uint32_t& r3, uint32_t a) {
    asm volatile("ldmatrix.sync.aligned.m8n8.x4.shared.b16 {%0,%1,%2,%3}, [%4];"
                 : "=r"(r0), "=r"(r1), "=r"(r2), "=r"(r3) : "r"(a));
}
// bf16 x bf16 -> f32 accum
__device__ __forceinline__ void mma_bf16_f32(float* c, const uint32_t* a, const uint32_t* b) {
    asm volatile(
        "mma.sync.aligned.m16n8k16.row.col.f32.bf16.bf16.f32 "
        "{%0,%1,%2,%3},{%4,%5,%6,%7},{%8,%9},{%0,%1,%2,%3};"
        : "+f"(c[0]), "+f"(c[1]), "+f"(c[2]), "+f"(c[3])
        : "r"(a[0]), "r"(a[1]), "r"(a[2]), "r"(a[3]), "r"(b[0]), "r"(b[1]));
}
// f16 x f16 -> f16 accum (2 packed-half regs)
__device__ __forceinline__ void mma_f16_f16(uint32_t* c, const uint32_t* a, const uint32_t* b) {
    asm volatile(
        "mma.sync.aligned.m16n8k16.row.col.f16.f16.f16.f16 "
        "{%0,%1},{%2,%3,%4,%5},{%6,%7},{%0,%1};"
        : "+r"(c[0]), "+r"(c[1])
        : "r"(a[0]), "r"(a[1]), "r"(a[2]), "r"(a[3]), "r"(b[0]), "r"(b[1]));
}

// ---------------------------------------------------------------------------
// GEMM: C[m,n] = sum_k A[m][k] * BT[n][k]
//   FT: 0 = bf16/f32acc, 2 = fp16/f16acc
//   EPI: 0 = bf16 store + stats, 1 = f32 store + bias + stats, 2 = bf16 spike
// CTA tile 128x128, K-step 32, 8 warps (64x32 per warp), double-buffered.
// ---------------------------------------------------------------------------
template<int FT, int EPI>
__global__ void __launch_bounds__(256)
gemm_mma(const uint16_t* __restrict__ A, int lda, long sA,
         const uint16_t* __restrict__ BT, int ldb, long sB,
         void* __restrict__ Cout, int ldc, long sC,
         int K, const float* __restrict__ bias,
         float* __restrict__ ssum, float* __restrict__ ssum2)
{
    constexpr int LDS = 40;
    __shared__ uint16_t As[2][128 * LDS];
    __shared__ uint16_t Bs[2][128 * LDS];

    const int bz = blockIdx.z;
    const uint16_t* Ab = A + (long)bz * sA;
    const uint16_t* Bb = BT + (long)bz * sB;
    const int m0 = blockIdx.y * 128, n0 = blockIdx.x * 128;
    const int tid = threadIdx.x;
    const int lane = tid & 31, warp = tid >> 5;
    const int wm = (warp & 1) * 64, wn = (warp >> 1) * 32;

    float    accf[FT == 0 ? 4 : 1][4][4];
    uint32_t acch[FT == 2 ? 4 : 1][4][2];
    if constexpr (FT == 0) {
#pragma unroll
        for (int i = 0; i < 4; i++)
#pragma unroll
            for (int j = 0; j < 4; j++)
#pragma unroll
                for (int r = 0; r < 4; r++) accf[i][j][r] = 0.f;
    } else {
#pragma unroll
        for (int i = 0; i < 4; i++)
#pragma unroll
            for (int j = 0; j < 4; j++) { acch[i][j][0] = 0u; acch[i][j][1] = 0u; }
    }

    auto issue = [&](int st, int k0) {
#pragma unroll
        for (int i = 0; i < 2; i++) {
            int c = tid + i * 256;
            int row = c >> 2, kc = (c & 3) << 3;
            cp_async16(smem_u32(&As[st][row * LDS + kc]),
                       Ab + (long)(m0 + row) * lda + k0 + kc);
            cp_async16(smem_u32(&Bs[st][row * LDS + kc]),
                       Bb + (long)(n0 + row) * ldb + k0 + kc);
        }
        asm volatile("cp.async.commit_group;");
    };

    const int KT = K / 32;
    issue(0, 0);
    for (int kt = 0; kt < KT; kt++) {
        if (kt + 1 < KT) {
            issue((kt + 1) & 1, (kt + 1) * 32);
            asm volatile("cp.async.wait_group 1;");
        } else {
            asm volatile("cp.async.wait_group 0;");
        }
        __syncthreads();
        const uint16_t* as = As[kt & 1];
        const uint16_t* bs = Bs[kt & 1];
#pragma unroll
        for (int kk = 0; kk < 2; kk++) {
            uint32_t af[4][4], bf[4][2];
#pragma unroll
            for (int mt = 0; mt < 4; mt++) {
                int row = wm + mt * 16 + (lane & 15);
                int kcol = kk * 16 + (lane >> 4) * 8;
                ldm_x4(af[mt][0], af[mt][1], af[mt][2], af[mt][3],
                       smem_u32(&as[row * LDS + kcol]));
            }
#pragma unroll
            for (int p = 0; p < 2; p++) {
                int g = lane >> 3;
                int row = wn + p * 16 + (g >> 1) * 8 + (lane & 7);
                int kcol = kk * 16 + (g & 1) * 8;
                uint32_t r0, r1, r2, r3;
                ldm_x4(r0, r1, r2, r3, smem_u32(&bs[row * LDS + kcol]));
                bf[p * 2][0] = r0; bf[p * 2][1] = r1;
                bf[p * 2 + 1][0] = r2; bf[p * 2 + 1][1] = r3;
            }
#pragma unroll
            for (int mt = 0; mt < 4; mt++)
#pragma unroll
                for (int nt = 0; nt < 4; nt++) {
                    if constexpr (FT == 0) mma_bf16_f32(accf[mt][nt], af[mt], bf[nt]);
                    else                   mma_f16_f16(acch[mt][nt], af[mt], bf[nt]);
                }
        }
        __syncthreads();
    }

    // epilogue
#pragma unroll
    for (int mt = 0; mt < 4; mt++) {
        int row = m0 + wm + mt * 16 + (lane >> 2);
        float b0 = 0.f, b8 = 0.f;
        if (EPI == 1) { b0 = bias[row]; b8 = bias[row + 8]; }
        float sl = 0.f, ql = 0.f, sh = 0.f, qh = 0.f;
#pragma unroll
        for (int nt = 0; nt < 4; nt++) {
            int col = n0 + wn + nt * 8 + (lane & 3) * 2;
            float v0, v1, v2, v3;
            if constexpr (FT == 0) {
                v0 = accf[mt][nt][0]; v1 = accf[mt][nt][1];
                v2 = accf[mt][nt][2]; v3 = accf[mt][nt][3];
            } else {
                __half2 h0 = *(__half2*)&acch[mt][nt][0];
                __half2 h1 = *(__half2*)&acch[mt][nt][1];
                v0 = __low2float(h0); v1 = __high2float(h0);
                v2 = __low2float(h1); v3 = __high2float(h1);
            }
            if (EPI == 2) {
                __nv_bfloat16* Cb = (__nv_bfloat16*)Cout + (long)bz * sC;
                float s0 = ((v0 * 0.125f) / TAUf - 0.5f >= 0.f) ? 1.f : 0.f;
                float s1 = ((v1 * 0.125f) / TAUf - 0.5f >= 0.f) ? 1.f : 0.f;
                float s2 = ((v2 * 0.125f) / TAUf - 0.5f >= 0.f) ? 1.f : 0.f;
                float s3 = ((v3 * 0.125f) / TAUf - 0.5f >= 0.f) ? 1.f : 0.f;
                *(__nv_bfloat162*)&Cb[(long)row * ldc + col] = __floats2bfloat162_rn(s0, s1);
                *(__nv_bfloat162*)&Cb[(long)(row + 8) * ldc + col] = __floats2bfloat162_rn(s2, s3);
            } else if (EPI == 0) {
                __nv_bfloat16* Cb = (__nv_bfloat16*)Cout + (long)bz * sC;
                *(__nv_bfloat162*)&Cb[(long)row * ldc + col] = __floats2bfloat162_rn(v0, v1);
                *(__nv_bfloat162*)&Cb[(long)(row + 8) * ldc + col] = __floats2bfloat162_rn(v2, v3);
                sl += v0 + v1; ql = fmaf(v0, v0, fmaf(v1, v1, ql));
                sh += v2 + v3; qh = fmaf(v2, v2, fmaf(v3, v3, qh));
            } else {
                float* Cb = (float*)Cout + (long)bz * sC;
                float w0 = v0 + b0, w1 = v1 + b0, w2 = v2 + b8, w3 = v3 + b8;
                *(float2*)&Cb[(long)row * ldc + col] = make_float2(w0, w1);
                *(float2*)&Cb[(long)(row + 8) * ldc + col] = make_float2(w2, w3);
                sl += w0 + w1; ql = fmaf(w0, w0, fmaf(w1, w1, ql));
                sh += w2 + w3; qh = fmaf(w2, w2, fmaf(w3, w3, qh));
            }
        }
        if (EPI != 2) {
            sl += __shfl_xor_sync(0xffffffffu, sl, 1);
            sl += __shfl_xor_sync(0xffffffffu, sl, 2);
            ql += __shfl_xor_sync(0xffffffffu, ql, 1);
            ql += __shfl_xor_sync(0xffffffffu, ql, 2);
            sh += __shfl_xor_sync(0xffffffffu, sh, 1);
            sh += __shfl_xor_sync(0xffffffffu, sh, 2);
            qh += __shfl_xor_sync(0xffffffffu, qh, 1);
            qh += __shfl_xor_sync(0xffffffffu, qh, 2);
            if ((lane & 3) == 0) {
                atomicAdd(&ssum[row], sl);  atomicAdd(&ssum2[row], ql);
                atomicAdd(&ssum[row + 8], sh); atomicAdd(&ssum2[row + 8], qh);
            }
        }
    }
}

// ---------------------------------------------------------------------------
// weights conversion (qkv -> fp16, proj -> bf16) + zero stats
// ---------------------------------------------------------------------------
__global__ void __launch_bounds__(256)
convert_weights(const float* __restrict__ qw, const float* __restrict__ kw,
                const float* __restrict__ vw, const float* __restrict__ pw,
                __half* __restrict__ wqkv, __nv_bfloat16* __restrict__ pwo,
                float* __restrict__ ss, float* __restrict__ ss2)
{
    int i = blockIdx.x * 256 + threadIdx.x;
    wqkv[i]               = __float2half(qw[i]);
    wqkv[i + CC * CC]     = __float2half(kw[i]);
    wqkv[i + 2 * CC * CC] = __float2half(vw[i]);
    pwo[i]                = __float2bfloat16(pw[i]);
    if (i < 4 * CC) { ss[i] = 0.f; ss2[i] = 0.f; }
}

// finalize stats + fold affine (one fused kernel; sets chosen by idx/CC)
__global__ void __launch_bounds__(256)
finalize_fold(const float* __restrict__ ss, const float* __restrict__ ss2,
              float* __restrict__ mean, float* __restrict__ inv,
              const float* __restrict__ g0, const float* __restrict__ b0,
              const float* __restrict__ g1, const float* __restrict__ b1,
              const float* __restrict__ g2, const float* __restrict__ b2,
              int nch)
{
    int i = blockIdx.x * 256 + threadIdx.x;
    if (i < nch) {
        const float invn = 1.f / (float)(BB * NN);
        float m = ss[i] * invn;
        float var = ss2[i] * invn - m * m;
        float iv = rsqrtf(var + EPSf);
        int set = i >> 9, c = i & (CC - 1);
        const float* ga = (set == 0) ? g0 : (set == 1) ? g1 : g2;
        const float* be = (set == 0) ? b0 : (set == 1) ? b1 : b2;
        float g = ga[c] * iv;
        mean[i] = m - be[c] / g;
        inv[i] = g;
    }
}

// x [b][c][n] fp32 -> xT fp16 [b][n][c]
__global__ void __launch_bounds__(256)
xT_kernel(const float* __restrict__ x, __half* __restrict__ xT)
{
    __shared__ float t[32][33];
    int b = blockIdx.z, n0 = blockIdx.x * 32, c0 = blockIdx.y * 32;
    int tx = threadIdx.x, ty = threadIdx.y;
    const float* xb = x + (long)b * CC * NN;
    __half* ob = xT + (long)b * NN * CC;
#pragma unroll
    for (int i = 0; i < 32; i += 8)
        t[ty + i][tx] = xb[(long)(c0 + ty + i) * NN + n0 + tx];
    __syncthreads();
#pragma unroll
    for (int i = 0; i < 32; i += 8)
        ob[(long)(n0 + ty + i) * CC + c0 + tx] = __float2half(t[tx][ty + i]);
}

__global__ void __launch_bounds__(256)
spike_qT_kernel(const __nv_bfloat16* __restrict__ y, long bstride,
                const float* __restrict__ mean, const float* __restrict__ inv,
                __half* __restrict__ qT)
{
    __shared__ float t[32][33];
    int b = blockIdx.z, n0 = blockIdx.x * 32, c0 = blockIdx.y * 32;
    int tx = threadIdx.x, ty = threadIdx.y;
    const __nv_bfloat16* yb = y + (long)b * bstride;
#pragma unroll
    for (int i = 0; i < 32; i += 8) {
        int c = c0 + ty + i;
        float v = __bfloat162float(yb[(long)c * NN + n0 + tx]);
        float bn = inv[c] * (v - mean[c]);
        t[ty + i][tx] = (bn / TAUf - 1.0f >= 0.f) ? 1.f : 0.f;
    }
    __syncthreads();
    __half* ob = qT + (long)b * NN * CC;
#pragma unroll
    for (int i = 0; i < 32; i += 8)
        ob[(long)(n0 + ty + i) * CC + c0 + tx] = __float2half(t[tx][ty + i]);
}

__global__ void __launch_bounds__(256)
spike_pack_kernel(const __nv_bfloat16* __restrict__ y, long bstride,
                  const float* __restrict__ mean, const float* __restrict__ inv,
                  unsigned* __restrict__ bits)
{
    long t = (long)blockIdx.x * 256 + threadIdx.x;
    long e = t * 4;
    int b = (int)(e / ((long)CC * NN));
    long r = e - (long)b * CC * NN;
    int c = (int)(r >> 10);
    const __nv_bfloat16* p = y + (long)b * bstride + r;
    uint2 raw = *(const uint2*)p;
    __nv_bfloat162 p01 = *(__nv_bfloat162*)&raw.x;
    __nv_bfloat162 p23 = *(__nv_bfloat162*)&raw.y;
    float g = inv[c], m = mean[c];
    float v0 = __low2float(p01), v1 = __high2float(p01);
    float v2 = __low2float(p23), v3 = __high2float(p23);
    unsigned m0 = __ballot_sync(0xffffffffu, (g * (v0 - m)) / TAUf - 1.f >= 0.f);
    unsigned m1 = __ballot_sync(0xffffffffu, (g * (v1 - m)) / TAUf - 1.f >= 0.f);
    unsigned m2 = __ballot_sync(0xffffffffu, (g * (v2 - m)) / TAUf - 1.f >= 0.f);
    unsigned m3 = __ballot_sync(0xffffffffu, (g * (v3 - m)) / TAUf - 1.f >= 0.f);
    int lane = threadIdx.x & 31;
    long e0 = e - (long)lane * 4;
    unsigned w = (lane == 0) ? m0 : (lane == 1) ? m1 : (lane == 2) ? m2 : m3;
    if (lane < 4) bits[(e0 >> 5) + lane] = w;
}

__global__ void __launch_bounds__(256)
kv_popc_kernel(const unsigned* __restrict__ kb, const unsigned* __restrict__ vb,
               __half* __restrict__ kvT)
{
    __shared__ unsigned ks[32][65];
    __shared__ unsigned vs[32][65];
    const int bz = blockIdx.z;
    const int c0 = blockIdx.y * 64;
    const int d0 = blockIdx.x * 64;
    const unsigned* kbb = kb + (long)bz * CC * (NN / 32);
    const unsigned* vbb = vb + (long)bz * CC * (NN / 32);
    const int tid = threadIdx.x;
#pragma unroll
    for (int it = 0; it < 8; it++) {
        int idx = tid + it * 256;
        int r = idx >> 5, w = idx & 31;
        ks[w][r] = kbb[(long)(c0 + r) * 32 + w];
        vs[w][r] = vbb[(long)(d0 + r) * 32 + w];
    }
    __syncthreads();
    const int tm = (tid >> 4) * 4;
    const int tn = (tid & 15) * 4;
    int cnt[4][4];
#pragma unroll
    for (int i = 0; i < 4; i++)
#pragma unroll
        for (int j = 0; j < 4; j++) cnt[i][j] = 0;
#pragma unroll
    for (int w = 0; w < 32; w++) {
        unsigned a[4], b[4];
#pragma unroll
        for (int i = 0; i < 4; i++) a[i] = ks[w][tm + i];
#pragma unroll
        for (int j = 0; j < 4; j++) b[j] = vs[w][tn + j];
#pragma unroll
        for (int i = 0; i < 4; i++)
#pragma unroll
            for (int j = 0; j < 4; j++)
                cnt[i][j] += __popc(a[i] & b[j]);
    }
    __half* ob = kvT + (long)bz * CC * CC;
#pragma unroll
    for (int j = 0; j < 4; j++) {
        long base = (long)(d0 + tn + j) * CC + c0 + tm;
        __half2 p0 = __halves2half2(__float2half((float)cnt[0][j]),
                                    __float2half((float)cnt[1][j]));
        __half2 p1 = __halves2half2(__float2half((float)cnt[2][j]),
                                    __float2half((float)cnt[3][j]));
        *(__half2*)&ob[base] = p0;
        *(__half2*)&ob[base + 2] = p1;
    }
}

// finalize proj stats + fold + nothing else (proj set only)
__global__ void __launch_bounds__(256)
finalize_fold_proj(const float* __restrict__ ss, const float* __restrict__ ss2,
                   float* __restrict__ mean, float* __restrict__ inv,
                   const float* __restrict__ ga, const float* __restrict__ be)
{
    int i = blockIdx.x * 256 + threadIdx.x;
    if (i < CC) {
        const float invn = 1.f / (float)(BB * NN);
        float m = ss[i] * invn;
        float var = ss2[i] * invn - m * m;
        float iv = rsqrtf(var + EPSf);
        float g = ga[i] * iv;
        mean[i] = m - be[i] / g;
        inv[i] = g;
    }
}

__global__ void __launch_bounds__(256)
spike_final_kernel(const float* __restrict__ y,
                   const float* __restrict__ mean, const float* __restrict__ inv,
                   float* __restrict__ out)
{
    long t = (long)blockIdx.x * 256 + threadIdx.x;
    long e = t * 4;
    int c = (int)((e >> 10) & (CC - 1));
    float g = inv[c], m = mean[c];
    float4 v = *(const float4*)&y[e];
    float4 o;
    o.x = ((g * (v.x - m)) / TAUf - 1.f >= 0.f) ? 1.f : 0.f;
    o.y = ((g * (v.y - m)) / TAUf - 1.f >= 0.f) ? 1.f : 0.f;
    o.z = ((g * (v.z - m)) / TAUf - 1.f >= 0.f) ? 1.f : 0.f;
    o.w = ((g * (v.w - m)) / TAUf - 1.f >= 0.f) ? 1.f : 0.f;
    *(float4*)&out[e] = o;
}

// ---------------------------------------------------------------------------
extern "C" void kernel_launch(void* const* d_in, const int* in_sizes, int n_in,
                              void* d_out, int out_size)
{
    const float* x      = (const float*)d_in[0];
    const float* q_w    = (const float*)d_in[1];
    const float* q_g    = (const float*)d_in[2];
    const float* q_b    = (const float*)d_in[3];
    const float* k_w    = (const float*)d_in[4];
    const float* k_g    = (const float*)d_in[5];
    const float* k_b    = (const float*)d_in[6];
    const float* v_w    = (const float*)d_in[7];
    const float* v_g    = (const float*)d_in[8];
    const float* v_b    = (const float*)d_in[9];
    const float* p_w    = (const float*)d_in[10];
    const float* p_g    = (const float*)d_in[11];
    const float* p_beta = (const float*)d_in[12];
    const float* p_bias = (const float*)d_in[13];

    void* p;
    cudaGetSymbolAddress(&p, g_y);     __nv_bfloat16* gy    = (__nv_bfloat16*)p;
    cudaGetSymbolAddress(&p, g_xT);    __half*        gxT   = (__half*)p;
    cudaGetSymbolAddress(&p, g_qT);    __half*        gqT   = (__half*)p;
    cudaGetSymbolAddress(&p, g_kbits); unsigned*      gkb   = (unsigned*)p;
    cudaGetSymbolAddress(&p, g_vbits); unsigned*      gvb   = (unsigned*)p;
    cudaGetSymbolAddress(&p, g_kvT);   __half*        gkvT  = (__half*)p;
    cudaGetSymbolAddress(&p, g_attnT); __nv_bfloat16* gattT = (__nv_bfloat16*)p;
    cudaGetSymbolAddress(&p, g_proj);  float*         gpr   = (float*)p;
    cudaGetSymbolAddress(&p, g_wqkv);  __half*        gwqkv = (__half*)p;
    cudaGetSymbolAddress(&p, g_pw);    __nv_bfloat16* gpw   = (__nv_bfloat16*)p;
    cudaGetSymbolAddress(&p, g_ssum);  float*         gss   = (float*)p;
    cudaGetSymbolAddress(&p, g_ssum2); float*         gss2  = (float*)p;
    cudaGetSymbolAddress(&p, g_mean);  float*         gmean = (float*)p;
    cudaGetSymbolAddress(&p, g_inv);   float*         ginv  = (float*)p;

    const long sNC = (long)NN * CC;
    const long sCN = (long)CC * NN;
    const unsigned nblk4 = (unsigned)(BCN / 4 / 256);
    dim3 t32(32, 8);
    dim3 gT(NN / 32, CC / 32, BB);

    // 0) weights (+ zero stats), x transpose
    convert_weights<<<(CC * CC) / 256, 256>>>(q_w, k_w, v_w, p_w, gwqkv, gpw, gss, gss2);
    xT_kernel<<<gT, t32>>>(x, gxT);

    // 1) fused qkv conv GEMM (fp16/f16acc + stats): M=1536, N=1024, K=512
    gemm_mma<2, 0><<<dim3(NN / 128, 1536 / 128, BB), 256>>>(
        (const uint16_t*)gwqkv, CC, 0,
        (const uint16_t*)gxT, CC, sNC,
        gy, NN, SY, CC, nullptr, gss, gss2);

    // 2) finalize qkv stats + fold affine (fused)
    finalize_fold<<<6, 256>>>(gss, gss2, gmean, ginv,
                              q_g, q_b, k_g, k_b, v_g, v_b, 3 * CC);

    // 3) spikes: q -> fp16 transposed, k/v -> bitpacked
    spike_qT_kernel<<<gT, t32>>>(gy, SY, gmean, ginv, gqT);
    spike_pack_kernel<<<nblk4, 256>>>(gy + 1 * sCN, SY, gmean + 1 * CC, ginv + 1 * CC, gkb);
    spike_pack_kernel<<<nblk4, 256>>>(gy + 2 * sCN, SY, gmean + 2 * CC, ginv + 2 * CC, gvb);

    // 4) kv^T via popcount (fp16, exact)
    kv_popc_kernel<<<dim3(CC / 64, CC / 64, BB), 256>>>(gkb, gvb, gkvT);

    // 5) attn^T GEMM (fp16/f16acc, exact ints) + spike: M=1024, N=512, K=512
    gemm_mma<2, 2><<<dim3(CC / 128, NN / 128, BB), 256>>>(
        (const uint16_t*)gqT, CC, sNC,
        (const uint16_t*)gkvT, CC, (long)CC * CC,
        gattT, CC, sNC, CC, nullptr, nullptr, nullptr);

    // 6) proj GEMM (bf16/f32acc) + bias + stats: M=512, N=1024, K=512
    gemm_mma<0, 1><<<dim3(NN / 128, CC / 128, BB), 256>>>(
        (const uint16_t*)gpw, CC, 0,
        (const uint16_t*)gattT, CC, sNC,
        gpr, NN, sCN, CC, p_bias, gss + 3 * CC, gss2 + 3 * CC);

    // 7) finalize proj stats + final spike
    finalize_fold_proj<<<2, 256>>>(gss + 3 * CC, gss2 + 3 * CC,
                                   gmean + 3 * CC, ginv + 3 * CC, p_g, p_beta);
    spike_final_kernel<<<nblk4, 256>>>(gpr, gmean + 3 * CC, ginv + 3 * CC,
                                       (float*)d_out);
}